// round 15
// baseline (speedup 1.0000x reference)
#include <cuda_runtime.h>
#include <cstdint>

#define BATCH   32
#define SENT    128
#define EMB     768
#define DIM     1024
#define NW      10
#define NT      512
#define CLUSTER 4

// ---------------------------------------------------------------------------
// DSMEM helpers (mapa + st.shared::cluster)
// ---------------------------------------------------------------------------
__device__ __forceinline__ uint32_t smem_addr(const void* p) {
    return (uint32_t)__cvta_generic_to_shared(p);
}
__device__ __forceinline__ void st_cluster_f4(uint32_t laddr, int pr, float4 v) {
    uint32_t ra;
    asm volatile("mapa.shared::cluster.u32 %0, %1, %2;" : "=r"(ra) : "r"(laddr), "r"(pr));
    asm volatile("st.shared::cluster.v4.f32 [%0], {%1, %2, %3, %4};"
                 :: "r"(ra), "f"(v.x), "f"(v.y), "f"(v.z), "f"(v.w) : "memory");
}
__device__ __forceinline__ void st_cluster_f32(uint32_t laddr, int pr, float v) {
    uint32_t ra;
    asm volatile("mapa.shared::cluster.u32 %0, %1, %2;" : "=r"(ra) : "r"(laddr), "r"(pr));
    asm volatile("st.shared::cluster.f32 [%0], %1;" :: "r"(ra), "f"(v) : "memory");
}
#define CLUSTER_SYNC() do {                                         \
    asm volatile("barrier.cluster.arrive.aligned;" ::: "memory");   \
    asm volatile("barrier.cluster.wait.aligned;"   ::: "memory");   \
} while (0)

// ---------------------------------------------------------------------------
// Packed f32x2 helpers (sm_103a FFMA2 — PTX-only form)
// ---------------------------------------------------------------------------
__device__ __forceinline__ float2 ffma2(float2 a, float2 b, float2 c) {
    unsigned long long au = *reinterpret_cast<unsigned long long*>(&a);
    unsigned long long bu = *reinterpret_cast<unsigned long long*>(&b);
    unsigned long long cu = *reinterpret_cast<unsigned long long*>(&c);
    unsigned long long du;
    asm("fma.rn.f32x2 %0, %1, %2, %3;" : "=l"(du) : "l"(au), "l"(bu), "l"(cu));
    return *reinterpret_cast<float2*>(&du);
}
__device__ __forceinline__ float2 fmul2(float2 a, float2 b) {
    unsigned long long au = *reinterpret_cast<unsigned long long*>(&a);
    unsigned long long bu = *reinterpret_cast<unsigned long long*>(&b);
    unsigned long long du;
    asm("mul.rn.f32x2 %0, %1, %2;" : "=l"(du) : "l"(au), "l"(bu));
    return *reinterpret_cast<float2*>(&du);
}

// Local pair sweep (both amps of the butterfly in one thread).
//   M00 = p+iq, M01 = -r-iu, M10 = r-iu, M11 = p-iq   (M = RY*RX fused)
__device__ __forceinline__ void local_sweep(float2& vre, float2& vim,
                                            float p, float q, float r, float u) {
    float a0r = vre.x, a0i = vim.x, a1r = vre.y, a1i = vim.y;
    float n0r = p * a0r - q * a0i - r * a1r + u * a1i;
    float n0i = p * a0i + q * a0r - r * a1i - u * a1r;
    float n1r = r * a0r + u * a0i + p * a1r + q * a1i;
    float n1i = r * a0i - u * a0r + p * a1i - q * a1r;
    vre = make_float2(n0r, n1r);
    vim = make_float2(n0i, n1i);
}

// Cross-lane sweep via shuffle; both register amps share side coefficients.
__device__ __forceinline__ void shfl_sweep(float2& vre, float2& vim,
                                           int mask, int s,
                                           float p, float q, float r, float u) {
    float2 ore, oim;
    ore.x = __shfl_xor_sync(0xffffffffu, vre.x, mask);
    ore.y = __shfl_xor_sync(0xffffffffu, vre.y, mask);
    oim.x = __shfl_xor_sync(0xffffffffu, vim.x, mask);
    oim.y = __shfl_xor_sync(0xffffffffu, vim.y, mask);
    float qs = s ? -q : q;
    float rs = s ? r : -r;
    float2 P  = make_float2(p, p);
    float2 Qs = make_float2(qs, qs);
    float2 nQ = make_float2(-qs, -qs);
    float2 Rs = make_float2(rs, rs);
    float2 U  = make_float2(u, u);
    float2 nU = make_float2(-u, -u);
    float2 nre = ffma2(P, vre, ffma2(nQ, vim, ffma2(Rs, ore, fmul2(U, oim))));
    float2 nim = ffma2(P, vim, ffma2(Qs, vre, ffma2(Rs, oim, fmul2(nU, ore))));
    vre = nre; vim = nim;
}

// ---------------------------------------------------------------------------
// Clustered fused kernel: 4 CTAs per batch (grid = 128, cluster = 4).
//   A: MAX-MLP mean — each of 384 threads issues 16 independent LDG.128
//      at compile-time offsets BEFORE any arithmetic (forces ptxas to
//      front-batch; ~98KB in flight per CTA), then tree-reduces.
//      DSMEM all-gather of partials, fixed-order combine (bitwise-identical).
//   B: circuit in registers, redundant per CTA.
//   C: score over this CTA's 32 rows; all 12 row-loads batched before FMAs.
// Output: out[0..32) scores; out[32..32800) Re(e) (c64->f32 cast).
// ---------------------------------------------------------------------------
__global__ __launch_bounds__(NT, 1) __cluster_dims__(CLUSTER, 1, 1)
void fused_kernel(const float* __restrict__ x,
                  const float* __restrict__ thx,
                  const float* __restrict__ thy,
                  float* __restrict__ out) {
    __shared__ __align__(16) float4 psum[CLUSTER][192];      // mean partials
    __shared__ __align__(16) float reA[DIM], imA[DIM];       // p1 -> p2
    __shared__ __align__(16) float reB[DIM], imB[DIM];       // p2 -> p1
    __shared__ __align__(16) float4 tmp4[192];
    __shared__ float mp[NW], mq[NW], mr[NW], mu[NW];
    __shared__ float wsum[16];
    __shared__ float cpart[CLUSTER];

    const int b    = blockIdx.x >> 2;
    const int rank = blockIdx.x & 3;
    const int r0   = rank * 32;                // this CTA's sentence rows
    const int t = threadIdx.x;                 // 0..511
    const int lane = t & 31, w = t >> 5;       // 16 warps

    if (t < NW) {
        float c = cosf(thx[t]), s = sinf(thx[t]);
        float C = cosf(thy[t]), S = sinf(thy[t]);
        mp[t] = C * c;   // Re(M00)
        mq[t] = S * s;   // Im(M00)
        mr[t] = S * c;   // Re(M10)
        mu[t] = C * s;   // -Im(M10) = -Im(M01)
    }

    // ---- Phase A: batched-load partial means over this CTA's 32 rows ----
    const float4* xb4 = (const float4*)(x + (size_t)b * SENT * EMB);
    float4 ptot;
    if (t < 384) {
        const int col = (t < 192) ? t : t - 192;
        const int s0  = r0 + ((t < 192) ? 0 : 16);
        const float4* p = xb4 + (size_t)s0 * 192 + col;
        float4 v[16];
#pragma unroll
        for (int s = 0; s < 16; s++) v[s] = __ldg(p + s * 192);  // all in flight
#pragma unroll
        for (int d = 8; d >= 1; d >>= 1)
#pragma unroll
            for (int k = 0; k < d; k++) {
                v[k].x += v[k + d].x; v[k].y += v[k + d].y;
                v[k].z += v[k + d].z; v[k].w += v[k + d].w;
            }
        ptot = v[0];
        if (t >= 192) tmp4[col] = ptot;
    }
    __syncthreads();
    if (t < 192) {
        float4 hi = tmp4[t];
        ptot.x += hi.x; ptot.y += hi.y; ptot.z += hi.z; ptot.w += hi.w;
        uint32_t la = smem_addr(&psum[rank][t]);
#pragma unroll
        for (int pr = 0; pr < CLUSTER; pr++) st_cluster_f4(la, pr, ptot);
    }
    CLUSTER_SYNC();

    // identical fixed-order combine in all CTAs -> bitwise-identical mean
    if (t < 192) {
        float4 s0 = psum[0][t], s1 = psum[1][t], s2 = psum[2][t], s3 = psum[3][t];
        const float inv = 1.0f / SENT;
        ((float4*)reB)[t] = make_float4(
            (((s0.x + s1.x) + s2.x) + s3.x) * inv,
            (((s0.y + s1.y) + s2.y) + s3.y) * inv,
            (((s0.z + s1.z) + s2.z) + s3.z) * inv,
            (((s0.w + s1.w) + s2.w) + s3.w) * inv);
    } else if (t < 256) {
        ((float4*)reB)[t] = make_float4(0.f, 0.f, 0.f, 0.f);
    } else {
        ((float4*)imB)[t - 256] = make_float4(0.f, 0.f, 0.f, 0.f);
    }
    __syncthreads();

    // ---- Phase B: circuit in registers (redundant per CTA) ----
    const int n2   = (w << 2) | (lane >> 3);
    const int idxA = (((lane & 7) << 1) << 6) | n2;
    const int idxB = idxA | 64;
    const int pa = __popc(idxA & (idxA >> 1)) + (((idxA >> 9) & idxA) & 1);
    const int pb = __popc(idxB & (idxB >> 1)) + (((idxB >> 9) & idxB) & 1);
    const float sa = (pa & 1) ? -1.f : 1.f;
    const float sb = (pb & 1) ? -1.f : 1.f;

    float2 vre = ((float2*)reB)[t];
    float2 vim = ((float2*)imB)[t];

#pragma unroll
    for (int rep = 0; rep < 3; rep++) {
        // phase-1: amp bits 0..5 == wires 9..4
        local_sweep(vre, vim, mp[9], mq[9], mr[9], mu[9]);
#pragma unroll
        for (int k = 1; k <= 5; k++) {
            const int msk = 1 << (k - 1);
            const int s = (lane >> (k - 1)) & 1;
            const int wi = 9 - k;
            shfl_sweep(vre, vim, msk, s, mp[wi], mq[wi], mr[wi], mu[wi]);
        }
        ((float2*)reA)[t] = vre;
        ((float2*)imA)[t] = vim;
        __syncthreads();
        vre = make_float2(reA[idxA], reA[idxB]);
        vim = make_float2(imA[idxA], imA[idxB]);
        // phase-2: amp bits 6..9 == wires 3..0
        local_sweep(vre, vim, mp[3], mq[3], mr[3], mu[3]);
        shfl_sweep(vre, vim, 1, lane & 1,        mp[2], mq[2], mr[2], mu[2]);
        shfl_sweep(vre, vim, 2, (lane >> 1) & 1, mp[1], mq[1], mr[1], mu[1]);
        shfl_sweep(vre, vim, 4, (lane >> 2) & 1, mp[0], mq[0], mr[0], mu[0]);
        vre.x *= sa; vim.x *= sa;                // CZ diagonal (hoisted signs)
        vre.y *= sb; vim.y *= sb;
        reB[idxA] = vre.x; reB[idxB] = vre.y;
        imB[idxA] = vim.x; imB[idxB] = vim.y;
        __syncthreads();
        if (rep < 2) {
            vre = ((float2*)reB)[t];
            vim = ((float2*)imB)[t];
        }
    }

    // ---- write Re(e): each rank writes its own quarter (coalesced) ----
    {
        float* e_re = out + 32 + (size_t)b * DIM;
        const int base = rank * 256;
        if (t < 256) e_re[base + t] = reB[base + t];
    }

    // ---- Phase C: score over this CTA's 32 rows (warp: 2 rows) ----
    float4 er4[6], ei4[6];
#pragma unroll
    for (int k = 0; k < 6; k++) {
        er4[k] = ((const float4*)reB)[lane + 32 * k];
        ei4[k] = ((const float4*)imB)[lane + 32 * k];
    }
    // batch ALL 12 row loads (2 rows x 6 f4) before the FMAs
    const float4* row0 = xb4 + (size_t)(r0 + w * 2) * 192;
    const float4* row1 = row0 + 192;
    float4 xv[12];
#pragma unroll
    for (int k = 0; k < 6; k++) {
        xv[k]     = __ldg(row0 + lane + 32 * k);
        xv[6 + k] = __ldg(row1 + lane + 32 * k);
    }
    float acc = 0.f;
#pragma unroll
    for (int r = 0; r < 2; r++) {
        float ur = 0.f, ui = 0.f;
#pragma unroll
        for (int k = 0; k < 6; k++) {
            float4 xq = xv[r * 6 + k];
            ur = fmaf(xq.x, er4[k].x, ur); ui = fmaf(xq.x, ei4[k].x, ui);
            ur = fmaf(xq.y, er4[k].y, ur); ui = fmaf(xq.y, ei4[k].y, ui);
            ur = fmaf(xq.z, er4[k].z, ur); ui = fmaf(xq.z, ei4[k].z, ui);
            ur = fmaf(xq.w, er4[k].w, ur); ui = fmaf(xq.w, ei4[k].w, ui);
        }
#pragma unroll
        for (int off = 16; off; off >>= 1) {
            ur += __shfl_xor_sync(0xffffffffu, ur, off);
            ui += __shfl_xor_sync(0xffffffffu, ui, off);
        }
        acc = fmaf(ur, ur, fmaf(ui, ui, acc));
    }
    if (lane == 0) wsum[w] = acc;
    __syncthreads();
    if (t == 0) {
        float tot = 0.f;
#pragma unroll
        for (int i = 0; i < 16; i++) tot += wsum[i];   // fixed order
        st_cluster_f32(smem_addr(&cpart[rank]), 0, tot);
    }
    CLUSTER_SYNC();
    if (rank == 0 && t == 0) {
        float tot = ((cpart[0] + cpart[1]) + cpart[2]) + cpart[3]; // fixed order
        tot *= (1.0f / SENT);
        out[b] = fminf(fmaxf(tot, 0.f), 1.f);
    }
}

extern "C" void kernel_launch(void* const* d_in, const int* in_sizes, int n_in,
                              void* d_out, int out_size) {
    const float* x = nullptr;
    const float* th[2] = {nullptr, nullptr};
    int nth = 0;
    for (int i = 0; i < n_in; i++) {
        if (in_sizes[i] > 1024) x = (const float*)d_in[i];
        else if (nth < 2) th[nth++] = (const float*)d_in[i];
    }
    float* out = (float*)d_out;

    fused_kernel<<<BATCH * CLUSTER, NT>>>(x, th[0], th[1], out);
}

// round 16
// speedup vs baseline: 1.0226x; 1.0226x over previous
#include <cuda_runtime.h>
#include <cstdint>

#define BATCH   32
#define SENT    128
#define EMB     768
#define DIM     1024
#define NW      10
#define NT      512
#define CLUSTER 4

#define X_TILE_BYTES  (32 * EMB * 4)            /* 98304: 32 rows per CTA   */
#define PSUM_BYTES    (CLUSTER * 192 * 16)      /* 12288                    */
#define CIRC_BYTES    (4 * DIM * 4)             /* 16384: reA/imA/reB/imB   */
#define DYN_SMEM      (X_TILE_BYTES + PSUM_BYTES + CIRC_BYTES)   /* 126976 */

// ---------------------------------------------------------------------------
// SMEM / DSMEM / mbarrier helpers
// ---------------------------------------------------------------------------
__device__ __forceinline__ uint32_t smem_addr(const void* p) {
    return (uint32_t)__cvta_generic_to_shared(p);
}
__device__ __forceinline__ void st_cluster_f4(uint32_t laddr, int pr, float4 v) {
    uint32_t ra;
    asm volatile("mapa.shared::cluster.u32 %0, %1, %2;" : "=r"(ra) : "r"(laddr), "r"(pr));
    asm volatile("st.shared::cluster.v4.f32 [%0], {%1, %2, %3, %4};"
                 :: "r"(ra), "f"(v.x), "f"(v.y), "f"(v.z), "f"(v.w) : "memory");
}
__device__ __forceinline__ void st_cluster_f32(uint32_t laddr, int pr, float v) {
    uint32_t ra;
    asm volatile("mapa.shared::cluster.u32 %0, %1, %2;" : "=r"(ra) : "r"(laddr), "r"(pr));
    asm volatile("st.shared::cluster.f32 [%0], %1;" :: "r"(ra), "f"(v) : "memory");
}
#define CLUSTER_SYNC() do {                                         \
    asm volatile("barrier.cluster.arrive.aligned;" ::: "memory");   \
    asm volatile("barrier.cluster.wait.aligned;"   ::: "memory");   \
} while (0)

__device__ __forceinline__ void mbar_init(uint32_t mb, uint32_t cnt) {
    asm volatile("mbarrier.init.shared.b64 [%0], %1;" :: "r"(mb), "r"(cnt) : "memory");
}
__device__ __forceinline__ void mbar_expect_tx(uint32_t mb, uint32_t bytes) {
    asm volatile("mbarrier.arrive.expect_tx.shared.b64 _, [%0], %1;"
                 :: "r"(mb), "r"(bytes) : "memory");
}
__device__ __forceinline__ void bulk_ld(uint32_t dst, const void* src,
                                        uint32_t bytes, uint32_t mb) {
    asm volatile("cp.async.bulk.shared::cluster.global.mbarrier::complete_tx::bytes "
                 "[%0], [%1], %2, [%3];"
                 :: "r"(dst), "l"(src), "r"(bytes), "r"(mb) : "memory");
}
__device__ __forceinline__ void mbar_wait(uint32_t mb, uint32_t parity) {
    uint32_t done;
    do {
        asm volatile("{\n\t.reg .pred p;\n\t"
                     "mbarrier.try_wait.parity.acquire.cta.shared::cta.b64 p, [%1], %2, 0x989680;\n\t"
                     "selp.b32 %0, 1, 0, p;\n\t}"
                     : "=r"(done) : "r"(mb), "r"(parity) : "memory");
    } while (!done);
}

// ---------------------------------------------------------------------------
// Packed f32x2 helpers (sm_103a FFMA2 — PTX-only form)
// ---------------------------------------------------------------------------
__device__ __forceinline__ float2 ffma2(float2 a, float2 b, float2 c) {
    unsigned long long au = *reinterpret_cast<unsigned long long*>(&a);
    unsigned long long bu = *reinterpret_cast<unsigned long long*>(&b);
    unsigned long long cu = *reinterpret_cast<unsigned long long*>(&c);
    unsigned long long du;
    asm("fma.rn.f32x2 %0, %1, %2, %3;" : "=l"(du) : "l"(au), "l"(bu), "l"(cu));
    return *reinterpret_cast<float2*>(&du);
}
__device__ __forceinline__ float2 fmul2(float2 a, float2 b) {
    unsigned long long au = *reinterpret_cast<unsigned long long*>(&a);
    unsigned long long bu = *reinterpret_cast<unsigned long long*>(&b);
    unsigned long long du;
    asm("mul.rn.f32x2 %0, %1, %2;" : "=l"(du) : "l"(au), "l"(bu));
    return *reinterpret_cast<float2*>(&du);
}

//   M00 = p+iq, M01 = -r-iu, M10 = r-iu, M11 = p-iq   (M = RY*RX fused)
__device__ __forceinline__ void local_sweep(float2& vre, float2& vim,
                                            float p, float q, float r, float u) {
    float a0r = vre.x, a0i = vim.x, a1r = vre.y, a1i = vim.y;
    float n0r = p * a0r - q * a0i - r * a1r + u * a1i;
    float n0i = p * a0i + q * a0r - r * a1i - u * a1r;
    float n1r = r * a0r + u * a0i + p * a1r + q * a1i;
    float n1i = r * a0i - u * a0r + p * a1i - q * a1r;
    vre = make_float2(n0r, n1r);
    vim = make_float2(n0i, n1i);
}

__device__ __forceinline__ void shfl_sweep(float2& vre, float2& vim,
                                           int mask, int s,
                                           float p, float q, float r, float u) {
    float2 ore, oim;
    ore.x = __shfl_xor_sync(0xffffffffu, vre.x, mask);
    ore.y = __shfl_xor_sync(0xffffffffu, vre.y, mask);
    oim.x = __shfl_xor_sync(0xffffffffu, vim.x, mask);
    oim.y = __shfl_xor_sync(0xffffffffu, vim.y, mask);
    float qs = s ? -q : q;
    float rs = s ? r : -r;
    float2 P  = make_float2(p, p);
    float2 Qs = make_float2(qs, qs);
    float2 nQ = make_float2(-qs, -qs);
    float2 Rs = make_float2(rs, rs);
    float2 U  = make_float2(u, u);
    float2 nU = make_float2(-u, -u);
    float2 nre = ffma2(P, vre, ffma2(nQ, vim, ffma2(Rs, ore, fmul2(U, oim))));
    float2 nim = ffma2(P, vim, ffma2(Qs, vre, ffma2(Rs, oim, fmul2(nU, ore))));
    vre = nre; vim = nim;
}

// ---------------------------------------------------------------------------
// Clustered fused kernel (grid=128, cluster=4, 1 CTA/SM, 124KB dyn smem):
//   0: ONE cp.async.bulk (TMA) pulls this CTA's contiguous 32-row x slab
//      (98304 B) into SMEM — x touches DRAM exactly once, no LDG anywhere.
//   A: column sums from SMEM; DSMEM all-gather; fixed-order combine.
//   B: circuit in registers (redundant per CTA).
//   C: score from the SMEM-resident slab (LDS, conflict-free).
// Output: out[0..32) scores; out[32..32800) Re(e) (c64->f32 cast).
// ---------------------------------------------------------------------------
__global__ __launch_bounds__(NT, 1) __cluster_dims__(CLUSTER, 1, 1)
void fused_kernel(const float* __restrict__ x,
                  const float* __restrict__ thx,
                  const float* __restrict__ thy,
                  float* __restrict__ out) {
    extern __shared__ __align__(16) unsigned char dsm[];
    float*  xs   = (float*)dsm;                                   // 24576 f
    float4* psum = (float4*)(dsm + X_TILE_BYTES);                 // [4][192]
    float*  reA  = (float*)(dsm + X_TILE_BYTES + PSUM_BYTES);
    float*  imA  = reA + DIM;
    float*  reB  = imA + DIM;
    float*  imB  = reB + DIM;

    __shared__ float mp[NW], mq[NW], mr[NW], mu[NW];
    __shared__ float wsum[16];
    __shared__ float cpart[CLUSTER];
    __shared__ __align__(8) uint64_t mbar;

    const int b    = blockIdx.x >> 2;
    const int rank = blockIdx.x & 3;
    const int t = threadIdx.x;                 // 0..511
    const int lane = t & 31, w = t >> 5;       // 16 warps

    const uint32_t mb = smem_addr(&mbar);

    // ---- kick off the bulk load first (overlap with setup) ----
    if (t == 0) mbar_init(mb, 1);
    __syncthreads();
    if (t == 0) {
        const float* src = x + (size_t)b * SENT * EMB + (size_t)rank * 32 * EMB;
        mbar_expect_tx(mb, X_TILE_BYTES);
        bulk_ld(smem_addr(xs), src, X_TILE_BYTES, mb);
    }

    if (t < NW) {
        float c = cosf(thx[t]), s = sinf(thx[t]);
        float C = cosf(thy[t]), S = sinf(thy[t]);
        mp[t] = C * c;   // Re(M00)
        mq[t] = S * s;   // Im(M00)
        mr[t] = S * c;   // Re(M10)
        mu[t] = C * s;   // -Im(M10) = -Im(M01)
    }

    mbar_wait(mb, 0);

    // ---- Phase A: column sums from SMEM (rows are local 0..31) ----
    float4 ptot;
    if (t < 384) {
        const int col = (t < 192) ? t : t - 192;
        const int s0  = (t < 192) ? 0 : 16;
        const float4* px = (const float4*)xs + (size_t)s0 * 192 + col;
        float4 a0 = make_float4(0.f,0.f,0.f,0.f), a1 = a0, a2 = a0, a3 = a0;
#pragma unroll
        for (int s = 0; s < 16; s += 4) {
            float4 v0 = px[(s + 0) * 192];
            float4 v1 = px[(s + 1) * 192];
            float4 v2 = px[(s + 2) * 192];
            float4 v3 = px[(s + 3) * 192];
            a0.x += v0.x; a0.y += v0.y; a0.z += v0.z; a0.w += v0.w;
            a1.x += v1.x; a1.y += v1.y; a1.z += v1.z; a1.w += v1.w;
            a2.x += v2.x; a2.y += v2.y; a2.z += v2.z; a2.w += v2.w;
            a3.x += v3.x; a3.y += v3.y; a3.z += v3.z; a3.w += v3.w;
        }
        ptot = make_float4((a0.x + a1.x) + (a2.x + a3.x),
                           (a0.y + a1.y) + (a2.y + a3.y),
                           (a0.z + a1.z) + (a2.z + a3.z),
                           (a0.w + a1.w) + (a2.w + a3.w));
        if (t >= 192) ((float4*)reA)[col] = ptot;   // reA free: scratch
    }
    __syncthreads();
    if (t < 192) {
        float4 hi = ((float4*)reA)[t];
        ptot.x += hi.x; ptot.y += hi.y; ptot.z += hi.z; ptot.w += hi.w;
        uint32_t la = smem_addr(&psum[rank * 192 + t]);
#pragma unroll
        for (int pr = 0; pr < CLUSTER; pr++) st_cluster_f4(la, pr, ptot);
    }
    CLUSTER_SYNC();

    // fixed-order combine in all CTAs -> bitwise-identical mean
    if (t < 192) {
        float4 s0 = psum[0 * 192 + t], s1 = psum[1 * 192 + t];
        float4 s2 = psum[2 * 192 + t], s3 = psum[3 * 192 + t];
        const float inv = 1.0f / SENT;
        ((float4*)reB)[t] = make_float4(
            (((s0.x + s1.x) + s2.x) + s3.x) * inv,
            (((s0.y + s1.y) + s2.y) + s3.y) * inv,
            (((s0.z + s1.z) + s2.z) + s3.z) * inv,
            (((s0.w + s1.w) + s2.w) + s3.w) * inv);
    } else if (t < 256) {
        ((float4*)reB)[t] = make_float4(0.f, 0.f, 0.f, 0.f);
    } else {
        ((float4*)imB)[t - 256] = make_float4(0.f, 0.f, 0.f, 0.f);
    }
    __syncthreads();

    // ---- Phase B: circuit in registers (redundant per CTA) ----
    const int n2   = (w << 2) | (lane >> 3);
    const int idxA = (((lane & 7) << 1) << 6) | n2;
    const int idxB = idxA | 64;
    const int pa = __popc(idxA & (idxA >> 1)) + (((idxA >> 9) & idxA) & 1);
    const int pb = __popc(idxB & (idxB >> 1)) + (((idxB >> 9) & idxB) & 1);
    const float sa = (pa & 1) ? -1.f : 1.f;
    const float sb = (pb & 1) ? -1.f : 1.f;

    float2 vre = ((float2*)reB)[t];
    float2 vim = ((float2*)imB)[t];

#pragma unroll
    for (int rep = 0; rep < 3; rep++) {
        // phase-1: amp bits 0..5 == wires 9..4
        local_sweep(vre, vim, mp[9], mq[9], mr[9], mu[9]);
#pragma unroll
        for (int k = 1; k <= 5; k++) {
            const int msk = 1 << (k - 1);
            const int s = (lane >> (k - 1)) & 1;
            const int wi = 9 - k;
            shfl_sweep(vre, vim, msk, s, mp[wi], mq[wi], mr[wi], mu[wi]);
        }
        ((float2*)reA)[t] = vre;
        ((float2*)imA)[t] = vim;
        __syncthreads();
        vre = make_float2(reA[idxA], reA[idxB]);
        vim = make_float2(imA[idxA], imA[idxB]);
        // phase-2: amp bits 6..9 == wires 3..0
        local_sweep(vre, vim, mp[3], mq[3], mr[3], mu[3]);
        shfl_sweep(vre, vim, 1, lane & 1,        mp[2], mq[2], mr[2], mu[2]);
        shfl_sweep(vre, vim, 2, (lane >> 1) & 1, mp[1], mq[1], mr[1], mu[1]);
        shfl_sweep(vre, vim, 4, (lane >> 2) & 1, mp[0], mq[0], mr[0], mu[0]);
        vre.x *= sa; vim.x *= sa;                // CZ diagonal (hoisted signs)
        vre.y *= sb; vim.y *= sb;
        reB[idxA] = vre.x; reB[idxB] = vre.y;
        imB[idxA] = vim.x; imB[idxB] = vim.y;
        __syncthreads();
        if (rep < 2) {
            vre = ((float2*)reB)[t];
            vim = ((float2*)imB)[t];
        }
    }

    // ---- write Re(e): each rank writes its own quarter (coalesced) ----
    {
        float* e_re = out + 32 + (size_t)b * DIM;
        const int base = rank * 256;
        if (t < 256) e_re[base + t] = reB[base + t];
    }

    // ---- Phase C: score over the SMEM slab (warp: local rows 2w, 2w+1) ----
    float4 er4[6], ei4[6];
#pragma unroll
    for (int k = 0; k < 6; k++) {
        er4[k] = ((const float4*)reB)[lane + 32 * k];
        ei4[k] = ((const float4*)imB)[lane + 32 * k];
    }
    const float4* xrow = (const float4*)xs + (size_t)(w * 2) * 192;
    float4 xv[12];
#pragma unroll
    for (int k = 0; k < 6; k++) {
        xv[k]     = xrow[lane + 32 * k];
        xv[6 + k] = xrow[192 + lane + 32 * k];
    }
    float acc = 0.f;
#pragma unroll
    for (int r = 0; r < 2; r++) {
        float ur = 0.f, ui = 0.f;
#pragma unroll
        for (int k = 0; k < 6; k++) {
            float4 xq = xv[r * 6 + k];
            ur = fmaf(xq.x, er4[k].x, ur); ui = fmaf(xq.x, ei4[k].x, ui);
            ur = fmaf(xq.y, er4[k].y, ur); ui = fmaf(xq.y, ei4[k].y, ui);
            ur = fmaf(xq.z, er4[k].z, ur); ui = fmaf(xq.z, ei4[k].z, ui);
            ur = fmaf(xq.w, er4[k].w, ur); ui = fmaf(xq.w, ei4[k].w, ui);
        }
#pragma unroll
        for (int off = 16; off; off >>= 1) {
            ur += __shfl_xor_sync(0xffffffffu, ur, off);
            ui += __shfl_xor_sync(0xffffffffu, ui, off);
        }
        acc = fmaf(ur, ur, fmaf(ui, ui, acc));
    }
    if (lane == 0) wsum[w] = acc;
    __syncthreads();
    if (t == 0) {
        float tot = 0.f;
#pragma unroll
        for (int i = 0; i < 16; i++) tot += wsum[i];   // fixed order
        st_cluster_f32(smem_addr(&cpart[rank]), 0, tot);
    }
    CLUSTER_SYNC();
    if (rank == 0 && t == 0) {
        float tot = ((cpart[0] + cpart[1]) + cpart[2]) + cpart[3]; // fixed order
        tot *= (1.0f / SENT);
        out[b] = fminf(fmaxf(tot, 0.f), 1.f);
    }
}

extern "C" void kernel_launch(void* const* d_in, const int* in_sizes, int n_in,
                              void* d_out, int out_size) {
    const float* x = nullptr;
    const float* th[2] = {nullptr, nullptr};
    int nth = 0;
    for (int i = 0; i < n_in; i++) {
        if (in_sizes[i] > 1024) x = (const float*)d_in[i];
        else if (nth < 2) th[nth++] = (const float*)d_in[i];
    }
    float* out = (float*)d_out;

    cudaFuncSetAttribute(fused_kernel,
                         cudaFuncAttributeMaxDynamicSharedMemorySize, DYN_SMEM);
    fused_kernel<<<BATCH * CLUSTER, NT, DYN_SMEM>>>(x, th[0], th[1], out);
}